// round 17
// baseline (speedup 1.0000x reference)
#include <cuda_runtime.h>
#include <cuda_bf16.h>
#include <math.h>
#include <stdint.h>

#define N_CLASS 32000
#define NH      1024
#define ENC     512
#define DEC     256

// ---------------- scratch (no allocations allowed) ----------------
__device__ float g_xw_enc[ENC * NH];
__device__ float g_enc_out[ENC * NH];
__device__ float g_enc_outT[NH * ENC];
__device__ float g_A[ENC * NH];
__device__ float g_xw_dec[DEC * NH];
__device__ float g_hcat[DEC * 2 * NH];                 // [h | ctx] rows
__device__ float g_S[DEC * ENC];
__device__ float g_W[DEC * ENC];
__device__ float g_h0[NH];
__device__ float g_zeros[NH];
__device__ float g_part[8 * 512 * 1024];
__device__ unsigned long long g_hbuf_enc[2][NH];
__device__ unsigned long long g_hbuf_dec[2][NH];

__global__ void init_kernel(const float* __restrict__ hidden) {
    int i = blockIdx.x * blockDim.x + threadIdx.x;
    if (i < NH) g_h0[i] = hidden[i];
    if (i < 2 * NH) {
        (&g_hbuf_enc[0][0])[i] = 0ULL;
        (&g_hbuf_dec[0][0])[i] = 0ULL;
    }
}

// ---------------- small helpers ----------------
__device__ __forceinline__ float tanh_fast(float x) {
    float e = __expf(2.f * x);
    return 1.f - 2.f / (e + 1.f);
}
__device__ __forceinline__ unsigned su32(const void* p) {
    return (unsigned)__cvta_generic_to_shared(p);
}
__device__ __forceinline__ void pub_tag(unsigned long long* p, float v, int tag) {
    unsigned long long pkt = ((unsigned long long)(unsigned)tag << 32)
                           | (unsigned long long)__float_as_uint(v);
    asm volatile("st.relaxed.gpu.global.b64 [%0], %1;" :: "l"(p), "l"(pkt) : "memory");
}
__device__ __forceinline__ unsigned long long ld_pkt(const unsigned long long* p) {
    unsigned long long v;
    asm volatile("ld.relaxed.gpu.global.b64 %0, [%1];" : "=l"(v) : "l"(p) : "memory");
    return v;
}
// quad poll: 4 independent loads per retry -> one L2 round trip for all
__device__ __forceinline__ void poll_tag4(const unsigned long long* p, int tag,
                                          float& v0, float& v1, float& v2, float& v3) {
    unsigned long long a, b, c, d;
    const unsigned ut = (unsigned)tag;
    do {
        a = ld_pkt(p);       b = ld_pkt(p + 256);
        c = ld_pkt(p + 512); d = ld_pkt(p + 768);
    } while ((unsigned)(a >> 32) != ut || (unsigned)(b >> 32) != ut ||
             (unsigned)(c >> 32) != ut || (unsigned)(d >> 32) != ut);
    v0 = __uint_as_float((unsigned)a);
    v1 = __uint_as_float((unsigned)b);
    v2 = __uint_as_float((unsigned)c);
    v3 = __uint_as_float((unsigned)d);
}

// ---------------- warp-MMA primitives (generic PTX -> HMMA) ----------------
__device__ __forceinline__ void ldm_x4(unsigned* r, unsigned addr) {
    asm volatile("ldmatrix.sync.aligned.m8n8.x4.shared.b16 {%0,%1,%2,%3}, [%4];"
                 : "=r"(r[0]), "=r"(r[1]), "=r"(r[2]), "=r"(r[3]) : "r"(addr));
}
__device__ __forceinline__ void ldm_x2(unsigned* r, unsigned addr) {
    asm volatile("ldmatrix.sync.aligned.m8n8.x2.shared.b16 {%0,%1}, [%2];"
                 : "=r"(r[0]), "=r"(r[1]) : "r"(addr));
}
__device__ __forceinline__ void mma_bf16(float* d, const unsigned* a, const unsigned* b) {
    asm volatile("mma.sync.aligned.m16n8k16.row.col.f32.bf16.bf16.f32 "
                 "{%0,%1,%2,%3}, {%4,%5,%6,%7}, {%8,%9}, {%0,%1,%2,%3};"
                 : "+f"(d[0]), "+f"(d[1]), "+f"(d[2]), "+f"(d[3])
                 : "r"(a[0]), "r"(a[1]), "r"(a[2]), "r"(a[3]), "r"(b[0]), "r"(b[1]));
}

// ---------------- bf16-split tensor GEMM pieces (128x128 tile, BK=64) ------------
#define BK        64
#define PADH      72
#define TILE_B    (128 * PADH * 2)       // 18432
#define STAGE_B   (4 * TILE_B)           // 73728
#define GEMM_SMEM (2 * STAGE_B)          // 147456

extern __shared__ unsigned char dynsh[];

__device__ __forceinline__ void ldg_tile(
    const float* __restrict__ src, int ld, int row0, long col0, int tid, float4* v)
{
    #pragma unroll
    for (int i = 0; i < 8; i++) {
        int j = tid + 256 * i;
        int r = j >> 4, c = j & 15;
        v[i] = *(const float4*)(src + (size_t)(row0 + r) * ld + col0 + c * 4);
    }
}

__device__ __forceinline__ void sts_tile_split(
    const float4* v, unsigned dst_hi, unsigned dst_lo, int tid)
{
    #pragma unroll
    for (int i = 0; i < 8; i++) {
        int j = tid + 256 * i;
        int r = j >> 4, c = j & 15;
        float4 t = v[i];
        __nv_bfloat162 h0 = __floats2bfloat162_rn(t.x, t.y);
        __nv_bfloat162 h1 = __floats2bfloat162_rn(t.z, t.w);
        float lx = t.x - __bfloat162float(h0.x);
        float ly = t.y - __bfloat162float(h0.y);
        float lz = t.z - __bfloat162float(h1.x);
        float lw = t.w - __bfloat162float(h1.y);
        __nv_bfloat162 l0 = __floats2bfloat162_rn(lx, ly);
        __nv_bfloat162 l1 = __floats2bfloat162_rn(lz, lw);
        unsigned boff = (unsigned)(r * PADH + c * 4) * 2;
        unsigned long long hv = ((unsigned long long)(*(unsigned*)&h1) << 32) | (*(unsigned*)&h0);
        unsigned long long lv = ((unsigned long long)(*(unsigned*)&l1) << 32) | (*(unsigned*)&l0);
        asm volatile("st.shared.b64 [%0], %1;" :: "r"(dst_hi + boff), "l"(hv) : "memory");
        asm volatile("st.shared.b64 [%0], %1;" :: "r"(dst_lo + boff), "l"(lv) : "memory");
    }
}

// core 128x128 mainloop + direct epilogue (bias). Used by fused kernels.
__device__ void gemm_body_direct(
    int m0, int n0,
    const float* __restrict__ Am, const float* __restrict__ Bm,
    const float* __restrict__ bias, float* __restrict__ C,
    int lda, int ldb, int ldc, int ntiles)
{
    const unsigned sbase = su32(dynsh);
    const int tid  = threadIdx.x;
    const int wid  = tid >> 5;
    const int lane = tid & 31;
    const int wr = wid >> 2;
    const int wc = wid & 3;

    float acc[4][4][4];
    #pragma unroll
    for (int mt = 0; mt < 4; mt++)
        #pragma unroll
        for (int nt = 0; nt < 4; nt++)
            #pragma unroll
            for (int q = 0; q < 4; q++) acc[mt][nt][q] = 0.f;

    const int arow = wr * 64 + (lane & 15);
    const int acolh = (lane >> 4) * 8;
    const int brow = wc * 32 + (lane & 7);
    const int bcolh = ((lane >> 3) & 1) * 8;

    float4 va[8], vb[8];
    ldg_tile(Am, lda, m0, 0, tid, va);
    ldg_tile(Bm, ldb, n0, 0, tid, vb);

    for (int kt = 0; kt < ntiles; kt++) {
        const unsigned bb = sbase + (unsigned)(kt & 1) * STAGE_B;
        const unsigned Ah = bb, Al = bb + TILE_B, Bh = bb + 2 * TILE_B, Bl = bb + 3 * TILE_B;

        sts_tile_split(va, Ah, Al, tid);
        sts_tile_split(vb, Bh, Bl, tid);
        __syncthreads();

        if (kt + 1 < ntiles) {
            long c0 = (long)(kt + 1) * BK;
            ldg_tile(Am, lda, m0, c0, tid, va);
            ldg_tile(Bm, ldb, n0, c0, tid, vb);
        }

        #pragma unroll
        for (int kk = 0; kk < 4; kk++) {
            unsigned a_hi[4][4], a_lo[4][4], b_hi[4][2], b_lo[4][2];
            #pragma unroll
            for (int mt = 0; mt < 4; mt++) {
                unsigned off = (unsigned)((arow + mt * 16) * PADH + kk * 16 + acolh) * 2;
                ldm_x4(a_hi[mt], Ah + off);
                ldm_x4(a_lo[mt], Al + off);
            }
            #pragma unroll
            for (int nt = 0; nt < 4; nt++) {
                unsigned off = (unsigned)((brow + nt * 8) * PADH + kk * 16 + bcolh) * 2;
                ldm_x2(b_hi[nt], Bh + off);
                ldm_x2(b_lo[nt], Bl + off);
            }
            #pragma unroll
            for (int mt = 0; mt < 4; mt++)
                #pragma unroll
                for (int nt = 0; nt < 4; nt++) {
                    mma_bf16(acc[mt][nt], a_hi[mt], b_hi[nt]);
                    mma_bf16(acc[mt][nt], a_hi[mt], b_lo[nt]);
                    mma_bf16(acc[mt][nt], a_lo[mt], b_hi[nt]);
                }
        }
    }

    const int g   = lane >> 2;
    const int tig = lane & 3;
    #pragma unroll
    for (int mt = 0; mt < 4; mt++) {
        int row = m0 + wr * 64 + mt * 16 + g;
        #pragma unroll
        for (int nt = 0; nt < 4; nt++) {
            int col = n0 + wc * 32 + nt * 8 + tig * 2;
            float b0 = bias[col], b1 = bias[col + 1];
            float2 v0 = {acc[mt][nt][0] + b0, acc[mt][nt][1] + b1};
            float2 v1 = {acc[mt][nt][2] + b0, acc[mt][nt][3] + b1};
            *(float2*)&C[(size_t)row * ldc + col] = v0;
            *(float2*)&C[(size_t)(row + 8) * ldc + col] = v1;
        }
    }
}

// ---------------- standalone GEMM kernel (split-K capable) — R14 config ----------
__global__ void __launch_bounds__(256, 1) gemm_mma(
    const float* __restrict__ Am, const float* __restrict__ Bm,
    const float* __restrict__ bias, float* __restrict__ Cdirect,
    float* __restrict__ partial,
    int M, int N, int lda, int ldb, int ldc,
    int kt_per_split, int kt_total)
{
    const unsigned sbase = su32(dynsh);
    const int tid  = threadIdx.x;
    const int wid  = tid >> 5;
    const int lane = tid & 31;
    const int n0 = blockIdx.x * 128;
    const int m0 = blockIdx.y * 128;
    const int s  = blockIdx.z;
    const long kt0 = (long)s * kt_per_split;
    int nt_ = kt_total - (int)kt0;
    if (nt_ > kt_per_split) nt_ = kt_per_split;
    const int ntiles = nt_;

    const int wr = wid >> 2;
    const int wc = wid & 3;

    float acc[4][4][4];
    #pragma unroll
    for (int mt = 0; mt < 4; mt++)
        #pragma unroll
        for (int nt = 0; nt < 4; nt++)
            #pragma unroll
            for (int q = 0; q < 4; q++) acc[mt][nt][q] = 0.f;

    const int arow = wr * 64 + (lane & 15);
    const int acolh = (lane >> 4) * 8;
    const int brow = wc * 32 + (lane & 7);
    const int bcolh = ((lane >> 3) & 1) * 8;

    float4 va[8], vb[8];
    ldg_tile(Am, lda, m0, kt0 * BK, tid, va);
    ldg_tile(Bm, ldb, n0, kt0 * BK, tid, vb);

    for (int kt = 0; kt < ntiles; kt++) {
        const unsigned bb = sbase + (unsigned)(kt & 1) * STAGE_B;
        const unsigned Ah = bb, Al = bb + TILE_B, Bh = bb + 2 * TILE_B, Bl = bb + 3 * TILE_B;

        sts_tile_split(va, Ah, Al, tid);
        sts_tile_split(vb, Bh, Bl, tid);
        __syncthreads();

        if (kt + 1 < ntiles) {
            long c0 = (kt0 + kt + 1) * BK;
            ldg_tile(Am, lda, m0, c0, tid, va);
            ldg_tile(Bm, ldb, n0, c0, tid, vb);
        }

        #pragma unroll
        for (int kk = 0; kk < 4; kk++) {
            unsigned a_hi[4][4], a_lo[4][4], b_hi[4][2], b_lo[4][2];
            #pragma unroll
            for (int mt = 0; mt < 4; mt++) {
                unsigned off = (unsigned)((arow + mt * 16) * PADH + kk * 16 + acolh) * 2;
                ldm_x4(a_hi[mt], Ah + off);
                ldm_x4(a_lo[mt], Al + off);
            }
            #pragma unroll
            for (int nt = 0; nt < 4; nt++) {
                unsigned off = (unsigned)((brow + nt * 8) * PADH + kk * 16 + bcolh) * 2;
                ldm_x2(b_hi[nt], Bh + off);
                ldm_x2(b_lo[nt], Bl + off);
            }
            #pragma unroll
            for (int mt = 0; mt < 4; mt++)
                #pragma unroll
                for (int nt = 0; nt < 4; nt++) {
                    mma_bf16(acc[mt][nt], a_hi[mt], b_hi[nt]);
                    mma_bf16(acc[mt][nt], a_hi[mt], b_lo[nt]);
                    mma_bf16(acc[mt][nt], a_lo[mt], b_hi[nt]);
                }
        }
    }

    const int g   = lane >> 2;
    const int tig = lane & 3;
    if (gridDim.z == 1) {
        #pragma unroll
        for (int mt = 0; mt < 4; mt++) {
            int row = m0 + wr * 64 + mt * 16 + g;
            #pragma unroll
            for (int nt = 0; nt < 4; nt++) {
                int col = n0 + wc * 32 + nt * 8 + tig * 2;
                float b0 = bias[col], b1 = bias[col + 1];
                float2 v0 = {acc[mt][nt][0] + b0, acc[mt][nt][1] + b1};
                float2 v1 = {acc[mt][nt][2] + b0, acc[mt][nt][3] + b1};
                *(float2*)&Cdirect[(size_t)row * ldc + col] = v0;
                *(float2*)&Cdirect[(size_t)(row + 8) * ldc + col] = v1;
            }
        }
    } else {
        #pragma unroll
        for (int mt = 0; mt < 4; mt++) {
            int row = m0 + wr * 64 + mt * 16 + g;
            float* pp = partial + ((size_t)s * M + row) * N;
            #pragma unroll
            for (int nt = 0; nt < 4; nt++) {
                int col = n0 + wc * 32 + nt * 8 + tig * 2;
                float2 v0 = {acc[mt][nt][0], acc[mt][nt][1]};
                float2 v1 = {acc[mt][nt][2], acc[mt][nt][3]};
                *(float2*)&pp[col] = v0;
                *(float2*)&pp[(size_t)8 * N + col] = v1;
            }
        }
    }
}

__global__ void reduce_splitk(const float* __restrict__ part,
                              const float* __restrict__ bias,
                              float* __restrict__ C, int MN, int N, int S)
{
    int i = blockIdx.x * 256 + threadIdx.x;
    if (i >= MN) return;
    float a = bias[i & (N - 1)];
    for (int s = 0; s < S; s++) a += part[(size_t)s * MN + i];
    C[i] = a;
}

// ---------------- 256-thread scan body (8 warps x 4 rows), shared by enc/dec ------
// ENC_MODE: steps=ENC, src xw=g_xw_enc, pub=g_hbuf_enc, out=g_enc_out(+T), seed=g_h0
// DEC_MODE: steps=DEC, src xw=g_xw_dec, pub=g_hbuf_dec, out=g_hcat h-half, seed=enc last h
template<int STEPS, bool ENC_MODE>
__device__ void scan_body(int c, const float* __restrict__ Whh,
                          const float* __restrict__ bhh, float* sh)
{
    const int tid  = threadIdx.x;      // 0..255
    const int p    = tid >> 5;
    const int lane = tid & 31;
    const int rbase = c * 32 + p * 4;

    float w0[32], w1[32], w2[32], w3[32];
    {
        const float* wp0 = Whh + (size_t)(rbase + 0) * NH + lane * 32;
        const float* wp1 = Whh + (size_t)(rbase + 1) * NH + lane * 32;
        const float* wp2 = Whh + (size_t)(rbase + 2) * NH + lane * 32;
        const float* wp3 = Whh + (size_t)(rbase + 3) * NH + lane * 32;
        #pragma unroll
        for (int j = 0; j < 8; j++) {
            int off = ((j + lane) & 7) * 4;
            #pragma unroll
            for (int k = 0; k < 4; k++) {
                w0[4*j+k] = wp0[off+k];
                w1[4*j+k] = wp1[off+k];
                w2[4*j+k] = wp2[off+k];
                w3[4*j+k] = wp3[off+k];
            }
        }
    }
    const float bsel = (lane < 4) ? bhh[rbase + lane] : 0.f;

    unsigned long long* const hb0 = ENC_MODE ? g_hbuf_enc[0] : g_hbuf_dec[0];
    unsigned long long* const hb1 = ENC_MODE ? g_hbuf_enc[1] : g_hbuf_dec[1];
    const float* const xw = ENC_MODE ? g_xw_enc : g_xw_dec;

    for (int t = 0; t < STEPS; t++) {
        float xwv = 0.f;
        if (lane < 4) xwv = __ldcg(&xw[(size_t)t * NH + rbase + lane]);

        if (t == 0) {
            const float* seed = ENC_MODE ? g_h0 : (g_enc_out + (size_t)(ENC - 1) * NH);
            *(float4*)&sh[tid * 4] = __ldcg((const float4*)seed + tid);
        } else {
            const unsigned long long* src = ((t - 1) & 1) ? hb1 : hb0;
            float v0, v1, v2, v3;
            poll_tag4(src + tid, t, v0, v1, v2, v3);
            sh[tid] = v0; sh[tid + 256] = v1; sh[tid + 512] = v2; sh[tid + 768] = v3;
        }
        __syncthreads();

        const float* shp = &sh[lane * 32];
        float a0 = 0.f, a1 = 0.f, a2 = 0.f, a3 = 0.f;
        #pragma unroll
        for (int j = 0; j < 8; j++) {
            float4 hv = *(const float4*)&shp[((j + lane) & 7) * 4];
            a0 = fmaf(w0[4*j+0], hv.x, a0); a1 = fmaf(w1[4*j+0], hv.x, a1);
            a2 = fmaf(w2[4*j+0], hv.x, a2); a3 = fmaf(w3[4*j+0], hv.x, a3);
            a0 = fmaf(w0[4*j+1], hv.y, a0); a1 = fmaf(w1[4*j+1], hv.y, a1);
            a2 = fmaf(w2[4*j+1], hv.y, a2); a3 = fmaf(w3[4*j+1], hv.y, a3);
            a0 = fmaf(w0[4*j+2], hv.z, a0); a1 = fmaf(w1[4*j+2], hv.z, a1);
            a2 = fmaf(w2[4*j+2], hv.z, a2); a3 = fmaf(w3[4*j+2], hv.z, a3);
            a0 = fmaf(w0[4*j+3], hv.w, a0); a1 = fmaf(w1[4*j+3], hv.w, a1);
            a2 = fmaf(w2[4*j+3], hv.w, a2); a3 = fmaf(w3[4*j+3], hv.w, a3);
        }
        #pragma unroll
        for (int o = 16; o > 0; o >>= 1) {
            a0 += __shfl_xor_sync(0xffffffffu, a0, o);
            a1 += __shfl_xor_sync(0xffffffffu, a1, o);
            a2 += __shfl_xor_sync(0xffffffffu, a2, o);
            a3 += __shfl_xor_sync(0xffffffffu, a3, o);
        }

        float accsel = (lane == 0) ? a0 : (lane == 1) ? a1 : (lane == 2) ? a2 : a3;
        if (lane < 4) {
            int r = rbase + lane;
            float h = tanh_fast(accsel + xwv + bsel);
            pub_tag(((t & 1) ? hb1 : hb0) + r, h, t + 1);
            if (ENC_MODE) {
                g_enc_out[(size_t)t * NH + r]   = h;
                g_enc_outT[(size_t)r * ENC + t] = h;
            } else {
                g_hcat[(size_t)t * 2 * NH + r] = h;
            }
        }
        __syncthreads();
    }
}

// ---------------- fused kernels: scan CTAs + independent GEMM CTAs ----------------
// fused_enc: CTA 0..31 enc_scan; CTA 32..47 dec_xw GEMM (M=256,N=1024,K=32000)
__global__ void __launch_bounds__(256, 1) fused_enc(
    const float* __restrict__ enc_W_hh, const float* __restrict__ enc_b_hh,
    const float* __restrict__ dec_input, const float* __restrict__ dec_W_ih,
    const float* __restrict__ dec_b_ih, float* __restrict__ xw_dec)
{
    __shared__ float sh[NH];
    int c = blockIdx.x;
    if (c < 32) {
        scan_body<ENC, true>(c, enc_W_hh, enc_b_hh, sh);
    } else {
        int g = c - 32;               // 0..15
        int m0 = (g >> 3) * 128;      // 0..1
        int n0 = (g & 7) * 128;       // 0..7
        gemm_body_direct(m0, n0, dec_input, dec_W_ih, dec_b_ih, xw_dec,
                         N_CLASS, N_CLASS, NH, 500);
    }
}

// fused_dec: CTA 0..31 dec_scan; CTA 32..63 A-GEMM (M=512,N=1024,K=1024)
__global__ void __launch_bounds__(256, 1) fused_dec(
    const float* __restrict__ dec_W_hh, const float* __restrict__ dec_b_hh,
    const float* __restrict__ attn_W, const float* __restrict__ attn_b,
    float* __restrict__ Aout)
{
    __shared__ float sh[NH];
    int c = blockIdx.x;
    if (c < 32) {
        scan_body<DEC, false>(c, dec_W_hh, dec_b_hh, sh);
    } else {
        int g = c - 32;               // 0..31
        int m0 = (g >> 3) * 128;      // 0..3
        int n0 = (g & 7) * 128;       // 0..7
        gemm_body_direct(m0, n0, g_enc_out, attn_W, attn_b, Aout,
                         NH, NH, NH, 16);
    }
}

// ---------------- batched row softmax over S[256,512] ----------------
__global__ void __launch_bounds__(512) softmax_kernel(float* __restrict__ attns)
{
    __shared__ float red[16];
    __shared__ float bc[2];
    const int t = blockIdx.x, tid = threadIdx.x, warp = tid >> 5, lane = tid & 31;

    float sc = g_S[(size_t)t * ENC + tid];
    float mx = sc;
    #pragma unroll
    for (int o = 16; o > 0; o >>= 1) mx = fmaxf(mx, __shfl_xor_sync(0xffffffffu, mx, o));
    if (lane == 0) red[warp] = mx;
    __syncthreads();
    if (tid < 16) {
        float v = red[tid];
        #pragma unroll
        for (int o = 8; o > 0; o >>= 1) v = fmaxf(v, __shfl_xor_sync(0xffffu, v, o));
        if (tid == 0) bc[0] = v;
    }
    __syncthreads();
    float e = __expf(sc - bc[0]);
    float sm = e;
    #pragma unroll
    for (int o = 16; o > 0; o >>= 1) sm += __shfl_xor_sync(0xffffffffu, sm, o);
    if (lane == 0) red[warp] = sm;
    __syncthreads();
    if (tid < 16) {
        float v = red[tid];
        #pragma unroll
        for (int o = 8; o > 0; o >>= 1) v += __shfl_xor_sync(0xffffu, v, o);
        if (tid == 0) bc[1] = v;
    }
    __syncthreads();
    float w = e / bc[1];
    g_W[(size_t)t * ENC + tid] = w;
    attns[(size_t)t * ENC + tid] = w;
}

// ---------------- launch ----------------
extern "C" void kernel_launch(void* const* d_in, const int* in_sizes, int n_in,
                              void* d_out, int out_size)
{
    const float* enc_input = (const float*)d_in[0];
    const float* hidden    = (const float*)d_in[1];
    const float* dec_input = (const float*)d_in[2];
    const float* enc_W_ih  = (const float*)d_in[3];
    const float* enc_W_hh  = (const float*)d_in[4];
    const float* enc_b_ih  = (const float*)d_in[5];
    const float* enc_b_hh  = (const float*)d_in[6];
    const float* dec_W_ih  = (const float*)d_in[7];
    const float* dec_W_hh  = (const float*)d_in[8];
    const float* dec_b_ih  = (const float*)d_in[9];
    const float* dec_b_hh  = (const float*)d_in[10];
    const float* attn_W    = (const float*)d_in[11];
    const float* attn_b    = (const float*)d_in[12];
    const float* out_W     = (const float*)d_in[13];
    const float* out_b     = (const float*)d_in[14];

    float* out   = (float*)d_out;
    float* outs  = out;                              // [256, 32000]
    float* attns = out + (size_t)DEC * N_CLASS;      // [256, 512]

    float *p_xw_enc, *p_enc_out, *p_enc_outT, *p_A, *p_xw_dec, *p_hcat,
          *p_S, *p_W, *p_part, *p_zeros;
    cudaGetSymbolAddress((void**)&p_xw_enc, g_xw_enc);
    cudaGetSymbolAddress((void**)&p_enc_out, g_enc_out);
    cudaGetSymbolAddress((void**)&p_enc_outT, g_enc_outT);
    cudaGetSymbolAddress((void**)&p_A, g_A);
    cudaGetSymbolAddress((void**)&p_xw_dec, g_xw_dec);
    cudaGetSymbolAddress((void**)&p_hcat, g_hcat);
    cudaGetSymbolAddress((void**)&p_S, g_S);
    cudaGetSymbolAddress((void**)&p_W, g_W);
    cudaGetSymbolAddress((void**)&p_part, g_part);
    cudaGetSymbolAddress((void**)&p_zeros, g_zeros);

    cudaFuncSetAttribute(gemm_mma,
                         cudaFuncAttributeMaxDynamicSharedMemorySize, GEMM_SMEM);
    cudaFuncSetAttribute(fused_enc,
                         cudaFuncAttributeMaxDynamicSharedMemorySize, GEMM_SMEM);
    cudaFuncSetAttribute(fused_dec,
                         cudaFuncAttributeMaxDynamicSharedMemorySize, GEMM_SMEM);

    init_kernel<<<8, 256>>>(hidden);

    // enc_xw : M=512,N=1024,K=32000, split 4
    gemm_mma<<<dim3(8, 4, 4), 256, GEMM_SMEM>>>(
        enc_input, enc_W_ih, nullptr, nullptr, p_part,
        ENC, NH, N_CLASS, N_CLASS, 0, 125, 500);
    reduce_splitk<<<(ENC * NH) / 256, 256>>>(p_part, enc_b_ih, p_xw_enc, ENC * NH, NH, 4);

    // fused: enc scan (32 CTAs) + dec_xw GEMM (16 CTAs, direct, hidden under scan)
    fused_enc<<<48, 256, GEMM_SMEM>>>(
        enc_W_hh, enc_b_hh, dec_input, dec_W_ih, dec_b_ih, p_xw_dec);

    // fused: dec scan (32 CTAs) + A-GEMM (32 CTAs, hidden under scan)
    fused_dec<<<64, 256, GEMM_SMEM>>>(
        dec_W_hh, dec_b_hh, attn_W, attn_b, p_A);

    // S = H @ A^T : M=256,N=512,K=1024 (H rows = g_hcat stride 2048)
    gemm_mma<<<dim3(4, 2, 1), 256, GEMM_SMEM>>>(
        p_hcat, p_A, p_zeros, p_S, nullptr,
        DEC, ENC, 2 * NH, NH, ENC, 16, 16);

    // row softmax -> g_W + attns
    softmax_kernel<<<DEC, 512>>>(attns);

    // ctx = W @ enc_out : M=256,N=1024,K=512 (B = enc_outT), C into g_hcat[:, NH:]
    gemm_mma<<<dim3(8, 2, 1), 256, GEMM_SMEM>>>(
        p_W, p_enc_outT, p_zeros, p_hcat + NH, nullptr,
        DEC, NH, ENC, ENC, 2 * NH, 8, 8);

    // outs = hcat @ out_W^T + out_b : M=256,N=32000,K=2048 direct
    gemm_mma<<<dim3(250, 2, 1), 256, GEMM_SMEM>>>(
        p_hcat, out_W, out_b, outs, nullptr,
        DEC, N_CLASS, 2 * NH, 2 * NH, N_CLASS, 32, 32);
}